// round 1
// baseline (speedup 1.0000x reference)
#include <cuda_runtime.h>
#include <cuda_bf16.h>
#include <cstdint>

#define BATCH 4096
#define MCOLS 4096
#define NROWS 4096
#define NNZ_PER_ROW 819
#define NNZ_TOTAL (NROWS * NNZ_PER_ROW)

#define BM 128
#define BN 128
#define BK 32
#define KSTEPS (MCOLS / BK)        // 128
#define SROW 36                    // padded smem row stride (floats) -> conflict-free LDS
#define TILE_FLOATS (128 * SROW)   // 4608 floats per tile buffer
#define SMEM_FLOATS (4 * TILE_FLOATS)  // A[2] + B[2] = 73728 bytes

// Dense W scratch. __device__ globals are zero-initialized at module load; the
// scatter writes the same values to the same (fixed CSR pattern) positions on
// every call, so zeros persist and replays are deterministic.
__device__ float g_Wdense[(size_t)NROWS * MCOLS];

__global__ void scatter_kernel(const float* __restrict__ val,
                               const int* __restrict__ rows,
                               const int* __restrict__ cols) {
    int i = blockIdx.x * blockDim.x + threadIdx.x;
    if (i < NNZ_TOTAL) {
        float v = val[i];
        uint32_t t;
        asm("cvt.rna.tf32.f32 %0, %1;" : "=r"(t) : "f"(v));  // pre-round W to tf32
        g_Wdense[(size_t)rows[i] * MCOLS + cols[i]] = __uint_as_float(t);
    }
}

__device__ __forceinline__ void cp16(uint32_t dst, const void* src) {
    asm volatile("cp.async.cg.shared.global [%0], [%1], 16;\n" :: "r"(dst), "l"(src));
}

__device__ __forceinline__ void prefetch_tiles(const float* __restrict__ x,
                                               int m0, int n0, int kt, int buf,
                                               uint32_t sA, uint32_t sB,
                                               int row, int seg) {
    const int k0 = kt * BK;
    #pragma unroll
    for (int it = 0; it < 4; ++it) {
        int r = row + it * 32;
        const float* ga = x + (size_t)(m0 + r) * MCOLS + k0 + seg * 4;
        const float* gb = g_Wdense + (size_t)(n0 + r) * MCOLS + k0 + seg * 4;
        uint32_t off = (uint32_t)((buf * TILE_FLOATS + r * SROW + seg * 4) * 4);
        cp16(sA + off, ga);
        cp16(sB + off, gb);
    }
    asm volatile("cp.async.commit_group;\n" ::);
}

__global__ void __launch_bounds__(256)
sgemm_tf32(const float* __restrict__ x, const float* __restrict__ bias,
           float* __restrict__ out) {
    extern __shared__ float smem[];
    float* As = smem;                       // [2][128][SROW]
    float* Bs = smem + 2 * TILE_FLOATS;     // [2][128][SROW]

    const int tid  = threadIdx.x;
    const int lane = tid & 31;
    const int warp = tid >> 5;
    const int wm = (warp & 3) * 32;   // warp m-offset (4 warps in M)
    const int wn = (warp >> 2) * 64;  // warp n-offset (2 warps in N)

    const int m0 = blockIdx.y * BM;
    const int n0 = blockIdx.x * BN;

    float acc[2][8][4];
    #pragma unroll
    for (int i = 0; i < 2; i++)
        #pragma unroll
        for (int j = 0; j < 8; j++)
            #pragma unroll
            for (int c = 0; c < 4; c++) acc[i][j][c] = 0.f;

    const uint32_t sA = (uint32_t)__cvta_generic_to_shared(As);
    const uint32_t sB = (uint32_t)__cvta_generic_to_shared(Bs);

    const int row = tid >> 3;   // 0..31  (x4 iterations -> 128 rows)
    const int seg = tid & 7;    // 0..7   (8 x 16B segments per 128B row)

    prefetch_tiles(x, m0, n0, 0, 0, sA, sB, row, seg);

    for (int kt = 0; kt < KSTEPS; ++kt) {
        const int cur = kt & 1;
        if (kt + 1 < KSTEPS) {
            prefetch_tiles(x, m0, n0, kt + 1, cur ^ 1, sA, sB, row, seg);
            asm volatile("cp.async.wait_group 1;\n" ::);
        } else {
            asm volatile("cp.async.wait_group 0;\n" ::);
        }
        __syncthreads();

        const float* Ac = As + cur * TILE_FLOATS;
        const float* Bc = Bs + cur * TILE_FLOATS;

        #pragma unroll
        for (int ks = 0; ks < 4; ++ks) {
            const int kk = ks * 8 + (lane & 3);

            uint32_t af[2][4];
            #pragma unroll
            for (int mt = 0; mt < 2; ++mt) {
                int r = wm + mt * 16 + (lane >> 2);
                float a0 = Ac[r * SROW + kk];
                float a1 = Ac[(r + 8) * SROW + kk];
                float a2 = Ac[r * SROW + kk + 4];
                float a3 = Ac[(r + 8) * SROW + kk + 4];
                asm("cvt.rna.tf32.f32 %0, %1;" : "=r"(af[mt][0]) : "f"(a0));
                asm("cvt.rna.tf32.f32 %0, %1;" : "=r"(af[mt][1]) : "f"(a1));
                asm("cvt.rna.tf32.f32 %0, %1;" : "=r"(af[mt][2]) : "f"(a2));
                asm("cvt.rna.tf32.f32 %0, %1;" : "=r"(af[mt][3]) : "f"(a3));
            }

            uint32_t bf[8][2];
            #pragma unroll
            for (int nt = 0; nt < 8; ++nt) {
                int n = wn + nt * 8 + (lane >> 2);
                bf[nt][0] = __float_as_uint(Bc[n * SROW + kk]);      // pre-rounded tf32
                bf[nt][1] = __float_as_uint(Bc[n * SROW + kk + 4]);
            }

            #pragma unroll
            for (int mt = 0; mt < 2; ++mt)
                #pragma unroll
                for (int nt = 0; nt < 8; ++nt) {
                    asm volatile(
                        "mma.sync.aligned.m16n8k8.row.col.f32.tf32.tf32.f32 "
                        "{%0,%1,%2,%3}, {%4,%5,%6,%7}, {%8,%9}, {%0,%1,%2,%3};"
                        : "+f"(acc[mt][nt][0]), "+f"(acc[mt][nt][1]),
                          "+f"(acc[mt][nt][2]), "+f"(acc[mt][nt][3])
                        : "r"(af[mt][0]), "r"(af[mt][1]),
                          "r"(af[mt][2]), "r"(af[mt][3]),
                          "r"(bf[nt][0]), "r"(bf[nt][1]));
                }
        }
        __syncthreads();
    }

    // Epilogue: out[b][n] = acc + bias[n]
    #pragma unroll
    for (int mt = 0; mt < 2; ++mt) {
        const int rbase = m0 + wm + mt * 16 + (lane >> 2);
        #pragma unroll
        for (int nt = 0; nt < 8; ++nt) {
            const int nbase = n0 + wn + nt * 8 + 2 * (lane & 3);
            const float b0 = bias[nbase];
            const float b1 = bias[nbase + 1];
            float2 v0 = make_float2(acc[mt][nt][0] + b0, acc[mt][nt][1] + b1);
            float2 v1 = make_float2(acc[mt][nt][2] + b0, acc[mt][nt][3] + b1);
            *(float2*)(out + (size_t)rbase * NROWS + nbase) = v0;
            *(float2*)(out + (size_t)(rbase + 8) * NROWS + nbase) = v1;
        }
    }
}

extern "C" void kernel_launch(void* const* d_in, const int* in_sizes, int n_in,
                              void* d_out, int out_size) {
    const float* x    = (const float*)d_in[0];   // [4096, 4096] fp32
    const float* wval = (const float*)d_in[1];   // [nnz] fp32
    const float* bias = (const float*)d_in[2];   // [4096] fp32
    const int*   rows = (const int*)d_in[3];     // [nnz] int32
    const int*   cols = (const int*)d_in[4];     // [nnz] int32
    float* out = (float*)d_out;                  // [4096, 4096] fp32

    scatter_kernel<<<(NNZ_TOTAL + 255) / 256, 256>>>(wval, rows, cols);

    const int smem_bytes = SMEM_FLOATS * (int)sizeof(float);  // 73728
    cudaFuncSetAttribute(sgemm_tf32,
                         cudaFuncAttributeMaxDynamicSharedMemorySize, smem_bytes);
    dim3 grid(NROWS / BN, BATCH / BM);
    sgemm_tf32<<<grid, 256, smem_bytes>>>(x, bias, out);
}